// round 1
// baseline (speedup 1.0000x reference)
#include <cuda_runtime.h>
#include <cuda_bf16.h>

// Problem sizes (fixed by the dataset)
#define B   16384
#define D   784
#define H   768
#define C   10
#define HW  (H/32)   // 24 words of 32 bits per row

// ---------------- device scratch (no allocations allowed) ----------------
__device__ float    g_h1[B * H];          // fc1 output (pre-BN)
__device__ unsigned g_bits1[B * HW];      // sign bits into fc2
__device__ unsigned g_bits2[B * HW];      // sign bits into fc3
__device__ float    g_h3[B * H];          // hardtanh(bn3(.)) real input to fc4
__device__ unsigned g_w2bits[HW * H];     // transposed [kword][j]
__device__ unsigned g_w3bits[HW * H];
__device__ float    g_s1[H], g_s2[H], g_s3[H];   // g * rsqrt(v+eps)

// ---------------- BN scale prep ----------------
__global__ void prep_scales(const float* __restrict__ g1, const float* __restrict__ v1,
                            const float* __restrict__ g2, const float* __restrict__ v2,
                            const float* __restrict__ g3, const float* __restrict__ v3) {
    int j = threadIdx.x;
    if (j < H) {
        // v + eps in fp32 (matches reference), correctly-rounded rsqrt via double
        float f1 = v1[j] + 1e-5f;
        float f2 = v2[j] + 1e-5f;
        float f3 = v3[j] + 1e-5f;
        g_s1[j] = g1[j] * (float)(1.0 / sqrt((double)f1));
        g_s2[j] = g2[j] * (float)(1.0 / sqrt((double)f2));
        g_s3[j] = g3[j] * (float)(1.0 / sqrt((double)f3));
    }
}

// ---------------- pack sign bits of W2 / W3, transposed [kword][j] ----------------
__global__ void pack_wbits(const float* __restrict__ W, int which) {
    int t = blockIdx.x * blockDim.x + threadIdx.x;  // over HW*H
    if (t >= HW * H) return;
    int kw = t / H, j = t % H;
    const float* p = &W[j * H + kw * 32];
    unsigned word = 0;
#pragma unroll
    for (int i = 0; i < 32; i++)
        word |= (p[i] >= 0.f ? 1u : 0u) << i;
    if (which == 0) g_w2bits[kw * H + j] = word;
    else            g_w3bits[kw * H + j] = word;
}

// ---------------- fc1: fp32 GEMM, C[b][j] = sum_k x[b][k]*sign(W1[j][k]) + b1[j] --------
#define BM 64
#define BN 64
#define BK 32
__global__ __launch_bounds__(256, 2)
void fc1_gemm(const float* __restrict__ X, const float* __restrict__ W1,
              const float* __restrict__ b1) {
    __shared__ float As[BK][BM + 4];   // transposed: As[k][m]
    __shared__ float Ws[BK][BN + 4];

    const int bm = blockIdx.y * BM;
    const int bn = blockIdx.x * BN;
    const int tid = threadIdx.x;
    const int ty = tid >> 4;           // 0..15
    const int tx = tid & 15;           // 0..15

    float acc[4][4];
#pragma unroll
    for (int i = 0; i < 4; i++)
#pragma unroll
        for (int j = 0; j < 4; j++) acc[i][j] = 0.f;

    for (int k0 = 0; k0 < D; k0 += BK) {
        // load A tile: 64 rows x 32 k  (512 float4, 2 per thread)
#pragma unroll
        for (int r = 0; r < 2; r++) {
            int q   = tid + 256 * r;
            int row = q >> 3;
            int kq  = (q & 7) * 4;
            int gk  = k0 + kq;
            float v0 = 0.f, v1 = 0.f, v2 = 0.f, v3 = 0.f;
            if (gk + 3 < D) {
                float4 v = *(const float4*)&X[(bm + row) * D + gk];
                v0 = v.x; v1 = v.y; v2 = v.z; v3 = v.w;
            } else {
                if (gk + 0 < D) v0 = X[(bm + row) * D + gk + 0];
                if (gk + 1 < D) v1 = X[(bm + row) * D + gk + 1];
                if (gk + 2 < D) v2 = X[(bm + row) * D + gk + 2];
                if (gk + 3 < D) v3 = X[(bm + row) * D + gk + 3];
            }
            As[kq + 0][row] = v0; As[kq + 1][row] = v1;
            As[kq + 2][row] = v2; As[kq + 3][row] = v3;
        }
        // load W tile (binarized on the fly, 0-padded beyond K)
#pragma unroll
        for (int r = 0; r < 2; r++) {
            int q   = tid + 256 * r;
            int row = q >> 3;
            int kq  = (q & 7) * 4;
            int gk  = k0 + kq;
            float v0 = 0.f, v1 = 0.f, v2 = 0.f, v3 = 0.f;
            if (gk + 3 < D) {
                float4 v = *(const float4*)&W1[(bn + row) * D + gk];
                v0 = (v.x >= 0.f) ? 1.f : -1.f;
                v1 = (v.y >= 0.f) ? 1.f : -1.f;
                v2 = (v.z >= 0.f) ? 1.f : -1.f;
                v3 = (v.w >= 0.f) ? 1.f : -1.f;
            } else {
                if (gk + 0 < D) v0 = (W1[(bn + row) * D + gk + 0] >= 0.f) ? 1.f : -1.f;
                if (gk + 1 < D) v1 = (W1[(bn + row) * D + gk + 1] >= 0.f) ? 1.f : -1.f;
                if (gk + 2 < D) v2 = (W1[(bn + row) * D + gk + 2] >= 0.f) ? 1.f : -1.f;
                if (gk + 3 < D) v3 = (W1[(bn + row) * D + gk + 3] >= 0.f) ? 1.f : -1.f;
            }
            Ws[kq + 0][row] = v0; Ws[kq + 1][row] = v1;
            Ws[kq + 2][row] = v2; Ws[kq + 3][row] = v3;
        }
        __syncthreads();

#pragma unroll
        for (int k = 0; k < BK; k++) {
            float4 a = *(const float4*)&As[k][ty * 4];
            float4 w = *(const float4*)&Ws[k][tx * 4];
            float av[4] = {a.x, a.y, a.z, a.w};
            float wv[4] = {w.x, w.y, w.z, w.w};
#pragma unroll
            for (int i = 0; i < 4; i++)
#pragma unroll
                for (int j = 0; j < 4; j++)
                    acc[i][j] += av[i] * wv[j];
        }
        __syncthreads();
    }

#pragma unroll
    for (int i = 0; i < 4; i++) {
        int row = bm + ty * 4 + i;
#pragma unroll
        for (int j = 0; j < 4; j++) {
            int col = bn + tx * 4 + j;
            g_h1[row * H + col] = acc[i][j] + b1[col];
        }
    }
}

// ---------------- pack1: BN threshold + sign-pack fc1 output ----------------
__global__ void pack1_kernel(const float* __restrict__ m1, const float* __restrict__ be1) {
    int idx = blockIdx.x * blockDim.x + threadIdx.x;   // over B*H
    int j = idx % H;
    float h = g_h1[idx];
    float bnv = (h - m1[j]) * g_s1[j] + be1[j];
    unsigned bal = __ballot_sync(0xffffffffu, bnv >= 0.f);
    if ((threadIdx.x & 31) == 0) g_bits1[idx >> 5] = bal;
}

// ---------------- fc2: XNOR-popcount + BN threshold -> bits2 ----------------
__global__ __launch_bounds__(256)
void fc2_kernel(const float* __restrict__ b2, const float* __restrict__ m2,
                const float* __restrict__ be2) {
    int w    = (blockIdx.x * blockDim.x + threadIdx.x) >> 5;
    int lane = threadIdx.x & 31;
    int b    = w / HW;
    int jw   = w % HW;
    int j    = jw * 32 + lane;

    unsigned a = 0;
    if (lane < HW) a = g_bits1[b * HW + lane];

    int cnt = 0;
#pragma unroll
    for (int k = 0; k < HW; k++) {
        unsigned aw = __shfl_sync(0xffffffffu, a, k);
        unsigned ww = g_w2bits[k * H + j];
        cnt += __popc(aw ^ ww);
    }
    float h   = (float)(H - 2 * cnt) + b2[j];
    float bnv = (h - m2[j]) * g_s2[j] + be2[j];
    unsigned bal = __ballot_sync(0xffffffffu, bnv >= 0.f);
    if (lane == 0) g_bits2[b * HW + jw] = bal;
}

// ---------------- fc3: XNOR-popcount + BN + hardtanh -> real h3 ----------------
__global__ __launch_bounds__(256)
void fc3_kernel(const float* __restrict__ b3, const float* __restrict__ m3,
                const float* __restrict__ be3) {
    int w    = (blockIdx.x * blockDim.x + threadIdx.x) >> 5;
    int lane = threadIdx.x & 31;
    int b    = w / HW;
    int jw   = w % HW;
    int j    = jw * 32 + lane;

    unsigned a = 0;
    if (lane < HW) a = g_bits2[b * HW + lane];

    int cnt = 0;
#pragma unroll
    for (int k = 0; k < HW; k++) {
        unsigned aw = __shfl_sync(0xffffffffu, a, k);
        unsigned ww = g_w3bits[k * H + j];
        cnt += __popc(aw ^ ww);
    }
    float h   = (float)(H - 2 * cnt) + b3[j];
    float bnv = (h - m3[j]) * g_s3[j] + be3[j];
    float ht  = fminf(fmaxf(bnv, -1.f), 1.f);
    g_h3[b * H + j] = ht;
}

// ---------------- fc4: real GEMV per row + log_softmax ----------------
__global__ __launch_bounds__(256)
void fc4_kernel(const float* __restrict__ W4, const float* __restrict__ b4,
                float* __restrict__ out) {
    int w    = (blockIdx.x * blockDim.x + threadIdx.x) >> 5;  // row index
    int lane = threadIdx.x & 31;

    float acc[C];
#pragma unroll
    for (int c = 0; c < C; c++) acc[c] = 0.f;

#pragma unroll
    for (int t = 0; t < HW; t++) {
        int k = t * 32 + lane;
        float hv = g_h3[w * H + k];
#pragma unroll
        for (int c = 0; c < C; c++)
            acc[c] += hv * W4[c * H + k];
    }
#pragma unroll
    for (int c = 0; c < C; c++) {
#pragma unroll
        for (int off = 16; off > 0; off >>= 1)
            acc[c] += __shfl_xor_sync(0xffffffffu, acc[c], off);
    }
    float lg[C];
    float mx = -3.402823466e+38f;
#pragma unroll
    for (int c = 0; c < C; c++) {
        lg[c] = acc[c] + b4[c];
        mx = fmaxf(mx, lg[c]);
    }
    float s = 0.f;
#pragma unroll
    for (int c = 0; c < C; c++) s += expf(lg[c] - mx);
    float lse = logf(s);
    if (lane < C) out[w * C + lane] = (lg[lane] - mx) - lse;
}

// ---------------- launch ----------------
extern "C" void kernel_launch(void* const* d_in, const int* in_sizes, int n_in,
                              void* d_out, int out_size) {
    const float* x   = (const float*)d_in[0];
    const float* W1  = (const float*)d_in[1];
    const float* b1  = (const float*)d_in[2];
    const float* W2  = (const float*)d_in[3];
    const float* b2  = (const float*)d_in[4];
    const float* W3  = (const float*)d_in[5];
    const float* b3  = (const float*)d_in[6];
    const float* W4  = (const float*)d_in[7];
    const float* b4  = (const float*)d_in[8];
    const float* g1  = (const float*)d_in[9];
    const float* be1 = (const float*)d_in[10];
    const float* m1  = (const float*)d_in[11];
    const float* v1  = (const float*)d_in[12];
    const float* g2  = (const float*)d_in[13];
    const float* be2 = (const float*)d_in[14];
    const float* m2  = (const float*)d_in[15];
    const float* v2  = (const float*)d_in[16];
    const float* g3  = (const float*)d_in[17];
    const float* be3 = (const float*)d_in[18];
    const float* m3  = (const float*)d_in[19];
    const float* v3  = (const float*)d_in[20];
    float* out = (float*)d_out;

    prep_scales<<<1, H>>>(g1, v1, g2, v2, g3, v3);

    int pwThreads = HW * H;
    pack_wbits<<<(pwThreads + 255) / 256, 256>>>(W2, 0);
    pack_wbits<<<(pwThreads + 255) / 256, 256>>>(W3, 1);

    dim3 g1grid(H / BN, B / BM);
    fc1_gemm<<<g1grid, 256>>>(x, W1, b1);

    pack1_kernel<<<(B * H) / 256, 256>>>(m1, be1);

    int warps = B * HW;                   // one warp per 32 outputs
    fc2_kernel<<<warps / 8, 256>>>(b2, m2, be2);
    fc3_kernel<<<warps / 8, 256>>>(b3, m3, be3);

    fc4_kernel<<<B / 8, 256>>>(W4, b4, out);
}

// round 3
// speedup vs baseline: 1.9354x; 1.9354x over previous
#include <cuda_runtime.h>
#include <cuda_bf16.h>
#include <cstdint>

#define B   16384
#define D   784
#define H   768
#define C   10
#define HW  24            // H/32
#define K2  2368          // 3*784 padded up to multiple of 64
#define NQ  592           // K2/4
#define NCH 37            // K2/64 k-chunks
#define TM  128
#define TN  128

// ---------------- device scratch ----------------
__device__ __align__(128) __nv_bfloat16 g_A[(size_t)B * K2];   // split activations
__device__ __align__(128) __nv_bfloat16 g_Wb[(size_t)H * K2];  // sign(W1) bf16, replicated 3x
__device__ unsigned g_bits1[B * HW];
__device__ unsigned g_bits2[B * HW];
__device__ float    g_h3[(size_t)B * H];
__device__ unsigned g_w2bits[HW * H];
__device__ unsigned g_w3bits[HW * H];
__device__ float g_sc1[H], g_of1[H], g_sc2[H], g_of2[H], g_sc3[H], g_of3[H];

#define SWZ(o) ((o) ^ (((o) >> 3) & 0x70))

__device__ __forceinline__ uint32_t smem_u32(const void* p) {
    uint32_t a;
    asm("{ .reg .u64 t; cvta.to.shared.u64 t, %1; cvt.u32.u64 %0, t; }" : "=r"(a) : "l"(p));
    return a;
}

// ---------------- prep: folded BN scales ----------------
__global__ void prep_scales(const float* b1, const float* g1, const float* m1, const float* be1, const float* v1,
                            const float* b2, const float* g2, const float* m2, const float* be2, const float* v2,
                            const float* b3, const float* g3, const float* m3, const float* be3, const float* v3) {
    int j = threadIdx.x;
    if (j >= H) return;
    float s1 = g1[j] * (float)(1.0 / sqrt((double)(v1[j] + 1e-5f)));
    float s2 = g2[j] * (float)(1.0 / sqrt((double)(v2[j] + 1e-5f)));
    float s3 = g3[j] * (float)(1.0 / sqrt((double)(v3[j] + 1e-5f)));
    g_sc1[j] = s1; g_of1[j] = (b1[j] - m1[j]) * s1 + be1[j];
    g_sc2[j] = s2; g_of2[j] = (b2[j] - m2[j]) * s2 + be2[j];
    g_sc3[j] = s3; g_of3[j] = (b3[j] - m3[j]) * s3 + be3[j];
}

// ---------------- prep: bit-pack W2 / W3 transposed [kword][j] ----------------
__global__ void pack_wbits(const float* __restrict__ W, int which) {
    int t = blockIdx.x * blockDim.x + threadIdx.x;
    if (t >= HW * H) return;
    int kw = t / H, j = t % H;
    const float* p = &W[j * H + kw * 32];
    unsigned word = 0;
#pragma unroll
    for (int i = 0; i < 32; i++) word |= (p[i] >= 0.f ? 1u : 0u) << i;
    if (which == 0) g_w2bits[kw * H + j] = word;
    else            g_w3bits[kw * H + j] = word;
}

// ---------------- prep: 3-term bf16 split of x ----------------
__global__ void prep_A(const float* __restrict__ X) {
    int idx = blockIdx.x * blockDim.x + threadIdx.x;
    if (idx >= B * NQ) return;
    int b = idx / NQ, q = idx - b * NQ;
    int kg = q * 4;
    __align__(8) __nv_bfloat16 o[4];
    if (kg >= 3 * D) {
        o[0] = o[1] = o[2] = o[3] = __float2bfloat16(0.f);
    } else {
        int r = kg / D;
        int k = kg - r * D;
        float4 xv = *(const float4*)&X[b * D + k];
        float xs[4] = {xv.x, xv.y, xv.z, xv.w};
#pragma unroll
        for (int i = 0; i < 4; i++) {
            float x = xs[i];
            __nv_bfloat16 h = __float2bfloat16_rn(x);
            if (r == 0) o[i] = h;
            else {
                float r1 = x - __bfloat162float(h);
                __nv_bfloat16 m = __float2bfloat16_rn(r1);
                if (r == 1) o[i] = m;
                else o[i] = __float2bfloat16_rn(r1 - __bfloat162float(m));
            }
        }
    }
    *(uint2*)&g_A[(size_t)b * K2 + kg] = *(uint2*)o;
}

// ---------------- prep: sign(W1) as bf16, replicated 3x ----------------
__global__ void prep_Wb(const float* __restrict__ W1) {
    int idx = blockIdx.x * blockDim.x + threadIdx.x;
    if (idx >= H * NQ) return;
    int j = idx / NQ, q = idx - j * NQ;
    int kg = q * 4;
    __align__(8) __nv_bfloat16 o[4];
    if (kg >= 3 * D) {
        o[0] = o[1] = o[2] = o[3] = __float2bfloat16(0.f);
    } else {
        int r = kg / D;
        int k = kg - r * D;
#pragma unroll
        for (int i = 0; i < 4; i++)
            o[i] = __float2bfloat16(W1[j * D + k + i] >= 0.f ? 1.f : -1.f);
    }
    *(uint2*)&g_Wb[(size_t)j * K2 + kg] = *(uint2*)o;
}

// ---------------- fc1: mma.sync bf16 GEMM + fused BN/sign/pack ----------------
// dyn smem: [0,512) sc, [512,1024) of, A0 @1024, A1 @17408, B0 @33792, B1 @50176
#define FC1_SMEM 66560
#define A_OFF(b) (1024u + (b) * 16384u)
#define B_OFF(b) (33792u + (b) * 16384u)

__global__ __launch_bounds__(256, 2)
void fc1_gemm() {
    extern __shared__ char smem[];
    const uint32_t sb = smem_u32(smem);
    const int tid = threadIdx.x;
    const int wid = tid >> 5, lane = tid & 31;
    const int warp_m = wid >> 2, warp_n = wid & 3;   // 2 x 4 warps, warp tile m64 n32
    const int bn = blockIdx.x * TN, bm = blockIdx.y * TM;

    float* ssc = (float*)(smem);
    float* sof = (float*)(smem + 512);
    if (tid < 128) { ssc[tid] = g_sc1[bn + tid]; sof[tid] = g_of1[bn + tid]; }

    const char* Abase = (const char*)g_A  + (size_t)bm * (K2 * 2);
    const char* Bbase = (const char*)g_Wb + (size_t)bn * (K2 * 2);

    float acc[4][4][4];
#pragma unroll
    for (int i = 0; i < 4; i++)
#pragma unroll
        for (int j = 0; j < 4; j++)
#pragma unroll
            for (int c = 0; c < 4; c++) acc[i][j][c] = 0.f;

    auto load_stage = [&](int s, int buf) {
        size_t kb = (size_t)s * 128;
        uint32_t adst = sb + A_OFF(buf), bdst = sb + B_OFF(buf);
#pragma unroll
        for (int i = 0; i < 4; i++) {
            int idx = i * 256 + tid;
            int row = idx >> 3, c = idx & 7;
            uint32_t off = SWZ((uint32_t)(row * 128 + c * 16));
            const char* srcA = Abase + (size_t)row * (K2 * 2) + kb + c * 16;
            const char* srcB = Bbase + (size_t)row * (K2 * 2) + kb + c * 16;
            asm volatile("cp.async.cg.shared.global [%0], [%1], 16;" :: "r"(adst + off), "l"(srcA));
            asm volatile("cp.async.cg.shared.global [%0], [%1], 16;" :: "r"(bdst + off), "l"(srcB));
        }
        asm volatile("cp.async.commit_group;");
    };

    auto compute = [&](int buf) {
        uint32_t ab = sb + A_OFF(buf), bb = sb + B_OFF(buf);
#pragma unroll
        for (int ks = 0; ks < 4; ks++) {
            uint32_t a[4][4], bf[2][4];
            const int kk = ks * 16 + (lane >> 4) * 8;      // k element offset for this lane
            const int mrow = warp_m * 64 + (lane & 15);
#pragma unroll
            for (int mf = 0; mf < 4; mf++) {
                uint32_t addr = ab + SWZ((uint32_t)((mrow + mf * 16) * 128 + kk * 2));
                asm volatile("ldmatrix.sync.aligned.m8n8.x4.shared.b16 {%0,%1,%2,%3}, [%4];"
                    : "=r"(a[mf][0]), "=r"(a[mf][1]), "=r"(a[mf][2]), "=r"(a[mf][3]) : "r"(addr));
            }
            const int nrow = warp_n * 32 + (lane & 15);
#pragma unroll
            for (int p = 0; p < 2; p++) {
                uint32_t addr = bb + SWZ((uint32_t)((nrow + p * 16) * 128 + kk * 2));
                asm volatile("ldmatrix.sync.aligned.m8n8.x4.shared.b16 {%0,%1,%2,%3}, [%4];"
                    : "=r"(bf[p][0]), "=r"(bf[p][1]), "=r"(bf[p][2]), "=r"(bf[p][3]) : "r"(addr));
            }
#pragma unroll
            for (int mf = 0; mf < 4; mf++)
#pragma unroll
                for (int nf = 0; nf < 4; nf++) {
                    uint32_t b0 = bf[nf >> 1][nf & 1], b1 = bf[nf >> 1][(nf & 1) + 2];
                    asm volatile(
                        "mma.sync.aligned.m16n8k16.row.col.f32.bf16.bf16.f32 "
                        "{%0,%1,%2,%3}, {%4,%5,%6,%7}, {%8,%9}, {%0,%1,%2,%3};"
                        : "+f"(acc[mf][nf][0]), "+f"(acc[mf][nf][1]),
                          "+f"(acc[mf][nf][2]), "+f"(acc[mf][nf][3])
                        : "r"(a[mf][0]), "r"(a[mf][1]), "r"(a[mf][2]), "r"(a[mf][3]),
                          "r"(b0), "r"(b1));
                }
        }
    };

    // 2-stage cp.async pipeline
    load_stage(0, 0);
    for (int s = 0; s < NCH; s++) {
        if (s + 1 < NCH) load_stage(s + 1, (s + 1) & 1);
        if (s + 1 < NCH) asm volatile("cp.async.wait_group 1;");
        else             asm volatile("cp.async.wait_group 0;");
        __syncthreads();
        compute(s & 1);
        __syncthreads();
    }

    // epilogue: BN + sign + bit-pack from register fragments
    const int tg = lane & 3, gid = lane >> 2;
    float scv[4][2], ofv[4][2];
#pragma unroll
    for (int nf = 0; nf < 4; nf++) {
        int cl = warp_n * 32 + nf * 8 + tg * 2;
        scv[nf][0] = ssc[cl];     ofv[nf][0] = sof[cl];
        scv[nf][1] = ssc[cl + 1]; ofv[nf][1] = sof[cl + 1];
    }
    const int widx = (bn >> 5) + warp_n;
#pragma unroll
    for (int mf = 0; mf < 4; mf++) {
        unsigned mA = 0, mB = 0;
#pragma unroll
        for (int nf = 0; nf < 4; nf++) {
            int p = nf * 8 + tg * 2;
            float f00 = fmaf(acc[mf][nf][0], scv[nf][0], ofv[nf][0]);
            float f01 = fmaf(acc[mf][nf][1], scv[nf][1], ofv[nf][1]);
            float f10 = fmaf(acc[mf][nf][2], scv[nf][0], ofv[nf][0]);
            float f11 = fmaf(acc[mf][nf][3], scv[nf][1], ofv[nf][1]);
            mA |= ((f00 >= 0.f ? 1u : 0u) << p) | ((f01 >= 0.f ? 1u : 0u) << (p + 1));
            mB |= ((f10 >= 0.f ? 1u : 0u) << p) | ((f11 >= 0.f ? 1u : 0u) << (p + 1));
        }
        mA |= __shfl_xor_sync(0xffffffffu, mA, 1); mA |= __shfl_xor_sync(0xffffffffu, mA, 2);
        mB |= __shfl_xor_sync(0xffffffffu, mB, 1); mB |= __shfl_xor_sync(0xffffffffu, mB, 2);
        if (tg == 0) {
            int row = bm + warp_m * 64 + mf * 16 + gid;
            g_bits1[row * HW + widx]       = mA;
            g_bits1[(row + 8) * HW + widx] = mB;
        }
    }
}

// ---------------- fc2 / fc3: XNOR-popcount, weights in smem ----------------
#define FC_SMEM (HW * H * 4 + 2 * H * 4)   // 79872

__global__ __launch_bounds__(256)
void fc2_kernel() {
    extern __shared__ char smem[];
    unsigned* ws = (unsigned*)smem;
    float* ssc = (float*)(smem + HW * H * 4);
    float* sof = ssc + H;
    const int tid = threadIdx.x, lane = tid & 31, wid = tid >> 5;
    for (int i = tid; i < HW * H; i += 256) ws[i] = g_w2bits[i];
    for (int i = tid; i < H; i += 256) { ssc[i] = g_sc2[i]; sof[i] = g_of2[i]; }
    __syncthreads();
    const int row0 = blockIdx.x * 64 + wid * 8;
#pragma unroll 1
    for (int rr = 0; rr < 8; rr++) {
        const int b = row0 + rr;
        const uint4* ap = (const uint4*)&g_bits1[b * HW];
        uint4 a0 = ap[0], a1 = ap[1], a2 = ap[2], a3 = ap[3], a4 = ap[4], a5 = ap[5];
        unsigned a[24] = {a0.x,a0.y,a0.z,a0.w, a1.x,a1.y,a1.z,a1.w, a2.x,a2.y,a2.z,a2.w,
                          a3.x,a3.y,a3.z,a3.w, a4.x,a4.y,a4.z,a4.w, a5.x,a5.y,a5.z,a5.w};
#pragma unroll 1
        for (int jw = 0; jw < HW; jw++) {
            const int j = jw * 32 + lane;
            int c0 = 0, c1 = 0;
#pragma unroll
            for (int k = 0; k < HW; k += 2) {
                c0 += __popc(a[k]     ^ ws[k * H + j]);
                c1 += __popc(a[k + 1] ^ ws[(k + 1) * H + j]);
            }
            float pop = (float)(H - 2 * (c0 + c1));
            float f = fmaf(pop, ssc[j], sof[j]);
            unsigned bal = __ballot_sync(0xffffffffu, f >= 0.f);
            if (lane == 0) g_bits2[b * HW + jw] = bal;
        }
    }
}

__global__ __launch_bounds__(256)
void fc3_kernel() {
    extern __shared__ char smem[];
    unsigned* ws = (unsigned*)smem;
    float* ssc = (float*)(smem + HW * H * 4);
    float* sof = ssc + H;
    const int tid = threadIdx.x, lane = tid & 31, wid = tid >> 5;
    for (int i = tid; i < HW * H; i += 256) ws[i] = g_w3bits[i];
    for (int i = tid; i < H; i += 256) { ssc[i] = g_sc3[i]; sof[i] = g_of3[i]; }
    __syncthreads();
    const int row0 = blockIdx.x * 64 + wid * 8;
#pragma unroll 1
    for (int rr = 0; rr < 8; rr++) {
        const int b = row0 + rr;
        const uint4* ap = (const uint4*)&g_bits2[b * HW];
        uint4 a0 = ap[0], a1 = ap[1], a2 = ap[2], a3 = ap[3], a4 = ap[4], a5 = ap[5];
        unsigned a[24] = {a0.x,a0.y,a0.z,a0.w, a1.x,a1.y,a1.z,a1.w, a2.x,a2.y,a2.z,a2.w,
                          a3.x,a3.y,a3.z,a3.w, a4.x,a4.y,a4.z,a4.w, a5.x,a5.y,a5.z,a5.w};
#pragma unroll 1
        for (int jw = 0; jw < HW; jw++) {
            const int j = jw * 32 + lane;
            int c0 = 0, c1 = 0;
#pragma unroll
            for (int k = 0; k < HW; k += 2) {
                c0 += __popc(a[k]     ^ ws[k * H + j]);
                c1 += __popc(a[k + 1] ^ ws[(k + 1) * H + j]);
            }
            float pop = (float)(H - 2 * (c0 + c1));
            float f = fmaf(pop, ssc[j], sof[j]);
            g_h3[(size_t)b * H + j] = fminf(fmaxf(f, -1.f), 1.f);
        }
    }
}

// ---------------- fc4: GEMV + log_softmax, W4 in smem ----------------
__global__ __launch_bounds__(256)
void fc4_kernel(const float* __restrict__ W4, const float* __restrict__ b4,
                float* __restrict__ out) {
    __shared__ float sW[C * H];
    const int tid = threadIdx.x, lane = tid & 31, wid = tid >> 5;
    for (int i = tid; i < C * H; i += 256) sW[i] = W4[i];
    __syncthreads();
    const int row0 = blockIdx.x * 32 + wid * 4;
#pragma unroll 1
    for (int rr = 0; rr < 4; rr++) {
        const int w = row0 + rr;
        float acc[C];
#pragma unroll
        for (int c = 0; c < C; c++) acc[c] = 0.f;
#pragma unroll
        for (int t = 0; t < HW; t++) {
            int k = t * 32 + lane;
            float hv = g_h3[(size_t)w * H + k];
#pragma unroll
            for (int c = 0; c < C; c++) acc[c] += hv * sW[c * H + k];
        }
#pragma unroll
        for (int c = 0; c < C; c++)
#pragma unroll
            for (int off = 16; off > 0; off >>= 1)
                acc[c] += __shfl_xor_sync(0xffffffffu, acc[c], off);
        float lg[C], mx = -3.402823466e+38f;
#pragma unroll
        for (int c = 0; c < C; c++) { lg[c] = acc[c] + b4[c]; mx = fmaxf(mx, lg[c]); }
        float s = 0.f;
#pragma unroll
        for (int c = 0; c < C; c++) s += expf(lg[c] - mx);
        float lse = logf(s);
        if (lane < C) out[w * C + lane] = (lg[lane] - mx) - lse;
    }
}

// ---------------- launch ----------------
extern "C" void kernel_launch(void* const* d_in, const int* in_sizes, int n_in,
                              void* d_out, int out_size) {
    const float* x   = (const float*)d_in[0];
    const float* W1  = (const float*)d_in[1];
    const float* b1  = (const float*)d_in[2];
    const float* W2  = (const float*)d_in[3];
    const float* b2  = (const float*)d_in[4];
    const float* W3  = (const float*)d_in[5];
    const float* b3  = (const float*)d_in[6];
    const float* W4  = (const float*)d_in[7];
    const float* b4  = (const float*)d_in[8];
    const float* g1  = (const float*)d_in[9];
    const float* be1 = (const float*)d_in[10];
    const float* m1  = (const float*)d_in[11];
    const float* v1  = (const float*)d_in[12];
    const float* g2  = (const float*)d_in[13];
    const float* be2 = (const float*)d_in[14];
    const float* m2  = (const float*)d_in[15];
    const float* v2  = (const float*)d_in[16];
    const float* g3  = (const float*)d_in[17];
    const float* be3 = (const float*)d_in[18];
    const float* m3  = (const float*)d_in[19];
    const float* v3  = (const float*)d_in[20];
    float* out = (float*)d_out;

    static bool attr_done = false;
    if (!attr_done) {
        cudaFuncSetAttribute(fc1_gemm,   cudaFuncAttributeMaxDynamicSharedMemorySize, FC1_SMEM);
        cudaFuncSetAttribute(fc2_kernel, cudaFuncAttributeMaxDynamicSharedMemorySize, FC_SMEM);
        cudaFuncSetAttribute(fc3_kernel, cudaFuncAttributeMaxDynamicSharedMemorySize, FC_SMEM);
        attr_done = true;
    }

    prep_scales<<<1, H>>>(b1, g1, m1, be1, v1, b2, g2, m2, be2, v2, b3, g3, m3, be3, v3);
    pack_wbits<<<(HW * H + 255) / 256, 256>>>(W2, 0);
    pack_wbits<<<(HW * H + 255) / 256, 256>>>(W3, 1);
    prep_A<<<(B * NQ + 255) / 256, 256>>>(x);
    prep_Wb<<<(H * NQ + 255) / 256, 256>>>(W1);

    fc1_gemm<<<dim3(H / TN, B / TM), 256, FC1_SMEM>>>();

    fc2_kernel<<<B / 64, 256, FC_SMEM>>>();
    fc3_kernel<<<B / 64, 256, FC_SMEM>>>();
    fc4_kernel<<<B / 32, 256>>>(W4, b4, out);
}